// round 13
// baseline (speedup 1.0000x reference)
#include <cuda_runtime.h>
#include <cstdint>

// ---------------- problem constants ----------------
#define BB 64
#define VOC 40
#define EMBD 32
#define L0N 512
#define L1N 1024
#define L2N 2048
#define NSUM (L0N + L1N + L2N)   // 3584
#define LATENT 512
#define STEPS 50
#define START_TOK 39
#define LOGITS_OFF (BB * STEPS)  // 3200

#define GRID 128
#define TPB  512

// ---------------- persistent device state (no allocation allowed) ----------------
__device__ float g_h0[BB * L0N];
__device__ float g_h1[BB * L1N];
__device__ float g_h2[BB * L2N];
__device__ float g_n0[BB * L0N];
__device__ float g_n1[BB * L1N];
__device__ float g_n2[BB * L2N];
__device__ float g_v0[BB * 2 * L0N];
__device__ float g_v1[BB * 2 * L1N];
__device__ float g_v2[BB * 2 * L2N];
__device__ float g_x[BB * EMBD];
__device__ int   g_done[BB];

// grid barrier state (monotonic generation; safe across graph replays) — R4-proven
__device__ unsigned          g_barcnt = 0;
__device__ volatile unsigned g_bargen = 0;

// ---------------- helpers ----------------
__device__ __forceinline__ void ffma2(uint64_t& d, uint64_t a, uint64_t b) {
    asm("fma.rn.f32x2 %0, %1, %2, %0;" : "+l"(d) : "l"(a), "l"(b));
}
__device__ __forceinline__ uint64_t pack2(float lo, float hi) {
    uint64_t r;
    asm("mov.b64 %0, {%1, %2};" : "=l"(r) : "f"(lo), "f"(hi));
    return r;
}
__device__ __forceinline__ void unpack2(uint64_t v, float& lo, float& hi) {
    asm("mov.b64 {%0, %1}, %2;" : "=f"(lo), "=f"(hi) : "l"(v));
}
__device__ __forceinline__ float sigmoidf_(float x) {
    return 1.0f / (1.0f + expf(-x));
}

// all 128 blocks are co-resident (GRID < 148 SMs) -> spin barrier is safe
__device__ __forceinline__ void grid_bar() {
    __syncthreads();
    if (threadIdx.x == 0) {
        unsigned gen = g_bargen;
        __threadfence();
        if (atomicAdd(&g_barcnt, 1u) == GRID - 1) {
            g_barcnt = 0;
            __threadfence();
            g_bargen = gen + 1;
        } else {
            while (g_bargen == gen) { }
            __threadfence();
        }
    }
    __syncthreads();
}

// ---------------- fused GEMM + activation phase (no cross-block split-K) ----------------
// Block = 1 column tile of TW = NCOL/GRID cols (full K), 64 rows.
// Threads: (pair 0..PAIRS-1) x (rowgroup 0..15, 4 rows each) x (ks 0..KS-1 k-slices).
// k-split partials reduced through smem in the epilogue; activation fused.
// ACT 0: gates  -> vbuf[row][j] = sigmoid(acc + bias[j])               (NCOL = 2*OUT)
// ACT 1: cand   -> nbuf[row][j] = z*h + (1-z)*tanh(acc + bias[j])      (NCOL = OUT)
//   cand staging input: [x, r*h], r = vbuf first half; z = vbuf second half.
template<int IN, int OUT, int NCOL, int ACT>
__device__ __forceinline__ void gemm_act(
    const float* __restrict__ W,
    const float* __restrict__ bias,
    const float* __restrict__ xsrc,
    const float* __restrict__ hbuf,
    float* __restrict__ vbuf,          // gates: output; cand: input (r,z)
    float* __restrict__ nbuf,          // cand: output
    uint64_t* __restrict__ s_x2)       // smem: 64*65 uint64
{
    constexpr int KTOT  = IN + OUT;
    constexpr int TW    = NCOL / GRID;          // 4..32 cols per block
    constexpr int PAIRS = TW / 2;               // 2..16 col-pairs
    constexpr int KS    = TPB / (PAIRS * 16);   // 2..16 k-slices
    constexpr int SUB   = 64 / KS;              // k's per slice per round
    constexpr int KC    = ((KTOT + KS - 1) / KS + SUB - 1) / SUB * SUB;
    constexpr int RNDS  = KC / SUB;

    const int tid  = threadIdx.x;
    const int pair = tid % PAIRS;
    const int rg   = (tid / PAIRS) & 15;
    const int ks   = tid / (PAIRS * 16);
    const int jbase = blockIdx.x * TW;

    const int kbeg = ks * KC;
    const int kend = (KTOT < (ks + 1) * KC) ? KTOT : (ks + 1) * KC;

    uint64_t acc[4] = {0ull, 0ull, 0ull, 0ull};
    const float* Wp = W + jbase + pair * 2;

    for (int rnd = 0; rnd < RNDS; rnd++) {
        __syncthreads();
        // stage 64 k-slots x 64 rows (slot s belongs to slice s/SUB)
        for (int idx = tid; idx < 64 * 64; idx += TPB) {
            const int s   = idx & 63;
            const int row = idx >> 6;
            const int gks = s / SUB;
            const int u   = s % SUB;
            const int kg  = gks * KC + rnd * SUB + u;
            const int ke  = (KTOT < (gks + 1) * KC) ? KTOT : (gks + 1) * KC;
            if (kg < ke) {
                float val;
                if (kg < IN) {
                    val = xsrc[row * IN + kg];
                } else {
                    const int q = kg - IN;
                    const float hv = hbuf[row * OUT + q];
                    val = (ACT == 1) ? vbuf[row * 2 * OUT + q] * hv : hv;
                }
                s_x2[s * 65 + row] = pack2(val, val);
            }
        }
        __syncthreads();

        const int kstart = kbeg + rnd * SUB;
        int ucnt = kend - kstart;
        ucnt = ucnt < 0 ? 0 : (ucnt > SUB ? SUB : ucnt);
#pragma unroll
        for (int u = 0; u < SUB; u++) {
            if (u < ucnt) {   // warp-uniform (ks uniform per warp)
                const uint64_t w =
                    *reinterpret_cast<const uint64_t*>(Wp + (size_t)(kstart + u) * NCOL);
                const uint64_t* xr = s_x2 + (ks * SUB + u) * 65 + (rg << 2);
                ffma2(acc[0], w, xr[0]);
                ffma2(acc[1], w, xr[1]);
                ffma2(acc[2], w, xr[2]);
                ffma2(acc[3], w, xr[3]);
            }
        }
    }

    // k-split reduction through smem (2048 u64 <= 64*65)
    __syncthreads();
#pragma unroll
    for (int r = 0; r < 4; r++) {
        const int row = (rg << 2) + r;
        s_x2[((pair << 6) + row) * KS + ks] = acc[r];
    }
    __syncthreads();

    // activation epilogue: one thread per (pair,row)
    for (int o = tid; o < PAIRS * 64; o += TPB) {
        const int pr  = o >> 6;
        const int row = o & 63;
        float s0 = 0.f, s1 = 0.f;
#pragma unroll
        for (int k2 = 0; k2 < KS; k2++) {
            float a, b;
            unpack2(s_x2[o * KS + k2], a, b);
            s0 += a; s1 += b;
        }
        const int j = jbase + pr * 2;
        if (ACT == 0) {
            vbuf[row * NCOL + j]     = sigmoidf_(s0 + bias[j]);
            vbuf[row * NCOL + j + 1] = sigmoidf_(s1 + bias[j + 1]);
        } else {
            const float c0 = tanhf(s0 + bias[j]);
            const float c1 = tanhf(s1 + bias[j + 1]);
            const float z0 = vbuf[row * 2 * OUT + OUT + j];
            const float z1 = vbuf[row * 2 * OUT + OUT + j + 1];
            const float h0 = hbuf[row * OUT + j];
            const float h1 = hbuf[row * OUT + j + 1];
            nbuf[row * OUT + j]     = z0 * h0 + (1.0f - z0) * c0;
            nbuf[row * OUT + j + 1] = z1 * h1 + (1.0f - z1) * c1;
        }
    }
    grid_bar();
}

// ---------------- one-time dense init: y = iv @ dense_W + dense_b -> h0|h1|h2 ----------------
__device__ __forceinline__ void dense_init(const float* __restrict__ iv,
                                           const float* __restrict__ dW,
                                           const float* __restrict__ db,
                                           const float* __restrict__ emb)
{
    // block 0 also initializes x / done
    if (blockIdx.x == 0) {
        for (int i = threadIdx.x; i < BB * EMBD; i += TPB)
            g_x[i] = emb[START_TOK * EMBD + (i & (EMBD - 1))];
        if (threadIdx.x < BB) g_done[threadIdx.x] = 0;
    }
    for (int o = blockIdx.x * TPB + threadIdx.x; o < BB * NSUM; o += GRID * TPB) {
        const int row = o / NSUM;
        const int col = o - row * NSUM;
        float s = 0.f;
        const float* ivr = iv + row * LATENT;
        const float* wc  = dW + col;
#pragma unroll 8
        for (int k = 0; k < LATENT; k++)
            s += ivr[k] * wc[(size_t)k * NSUM];
        s += db[col];
        if (col < L0N)             g_h0[row * L0N + col] = s;
        else if (col < L0N + L1N)  g_h1[row * L1N + (col - L0N)] = s;
        else                       g_h2[row * L2N + (col - L0N - L1N)] = s;
    }
    grid_bar();
}

// ---------------- decode phase (R4-exact: logits, argmax, masked writes, h/x update) ----------------
__device__ __forceinline__ void decode_phase(const float* __restrict__ decW,
                                             const float* __restrict__ emb,
                                             float* __restrict__ out, int step)
{
    if (blockIdx.x < BB) {
        __shared__ float s_logit[VOC];
        __shared__ int s_idx, s_d0;
        const int b    = blockIdx.x;
        const int tid  = threadIdx.x;
        const int w    = tid >> 5;      // 16 warps
        const int lane = tid & 31;

        if (w < 8) {   // 8 warps x 5 logit cols
            float acc[5];
#pragma unroll
            for (int jj = 0; jj < 5; jj++) acc[jj] = 0.0f;

            const float* n2row = g_n2 + b * L2N;
            for (int k = lane; k < L2N; k += 32) {
                const float xv = n2row[k];
                const float* wr = decW + k * VOC + w * 5;
#pragma unroll
                for (int jj = 0; jj < 5; jj++) acc[jj] += xv * wr[jj];
            }
#pragma unroll
            for (int jj = 0; jj < 5; jj++) {
                float s = acc[jj];
#pragma unroll
                for (int off = 16; off > 0; off >>= 1)
                    s += __shfl_down_sync(0xffffffffu, s, off);
                if (lane == 0) s_logit[w * 5 + jj] = s;
            }
        }
        __syncthreads();

        if (tid == 0) {
            const int d0 = g_done[b];
            float best = s_logit[0];
            int bi = 0;
            for (int jj = 1; jj < VOC; jj++) {
                const float lv = s_logit[jj];
                if (lv > best) { best = lv; bi = jj; }   // first-max on ties
            }
            s_idx = bi;
            s_d0  = d0;
            out[b * STEPS + step] = (float)(d0 ? 0 : bi);   // STOP_TOK == 0
            g_done[b] = d0 | (bi == 0);
        }
        __syncthreads();

        const int d0  = s_d0;
        const int idx = s_idx;

        float* lo = out + LOGITS_OFF + (b * STEPS + step) * VOC;
        for (int jj = tid; jj < VOC; jj += TPB)
            lo[jj] = d0 ? 0.0f : s_logit[jj];

        if (!d0) {
            for (int q = tid; q < L0N; q += TPB) g_h0[b * L0N + q] = g_n0[b * L0N + q];
            for (int q = tid; q < L1N; q += TPB) g_h1[b * L1N + q] = g_n1[b * L1N + q];
            for (int q = tid; q < L2N; q += TPB) g_h2[b * L2N + q] = g_n2[b * L2N + q];
            if (tid < EMBD) g_x[b * EMBD + tid] = emb[idx * EMBD + tid];
        }
    }
    grid_bar();
}

// ---------------- the single persistent kernel ----------------
__global__ void __launch_bounds__(TPB, 1) decoder_kernel(
    const float* __restrict__ iv,   const float* __restrict__ emb,
    const float* __restrict__ dW,   const float* __restrict__ db,
    const float* __restrict__ decW,
    const float* __restrict__ Kg0, const float* __restrict__ bg0,
    const float* __restrict__ Kc0, const float* __restrict__ bc0,
    const float* __restrict__ Kg1, const float* __restrict__ bg1,
    const float* __restrict__ Kc1, const float* __restrict__ bc1,
    const float* __restrict__ Kg2, const float* __restrict__ bg2,
    const float* __restrict__ Kc2, const float* __restrict__ bc2,
    float* __restrict__ out)
{
    __shared__ __align__(16) uint64_t s_x2[64 * 65];

    dense_init(iv, dW, db, emb);

    for (int s = 0; s < STEPS; s++) {
        // layer 0
        gemm_act<EMBD, L0N, 2 * L0N, 0>(Kg0, bg0, g_x,  g_h0, g_v0, nullptr, s_x2);
        gemm_act<EMBD, L0N, L0N,     1>(Kc0, bc0, g_x,  g_h0, g_v0, g_n0,    s_x2);
        // layer 1 (x = n0)
        gemm_act<L0N,  L1N, 2 * L1N, 0>(Kg1, bg1, g_n0, g_h1, g_v1, nullptr, s_x2);
        gemm_act<L0N,  L1N, L1N,     1>(Kc1, bc1, g_n0, g_h1, g_v1, g_n1,    s_x2);
        // layer 2 (x = n1)
        gemm_act<L1N,  L2N, 2 * L2N, 0>(Kg2, bg2, g_n1, g_h2, g_v2, nullptr, s_x2);
        gemm_act<L1N,  L2N, L2N,     1>(Kc2, bc2, g_n1, g_h2, g_v2, g_n2,    s_x2);

        decode_phase(decW, emb, out, s);
    }
}

// ---------------- launch ----------------
extern "C" void kernel_launch(void* const* d_in, const int* in_sizes, int n_in,
                              void* d_out, int out_size)
{
    const float* iv   = (const float*)d_in[0];
    const float* emb  = (const float*)d_in[1];
    const float* dW   = (const float*)d_in[2];
    const float* db   = (const float*)d_in[3];
    const float* decW = (const float*)d_in[4];
    const float* Kg0  = (const float*)d_in[5];
    const float* bg0  = (const float*)d_in[6];
    const float* Kc0  = (const float*)d_in[7];
    const float* bc0  = (const float*)d_in[8];
    const float* Kg1  = (const float*)d_in[9];
    const float* bg1  = (const float*)d_in[10];
    const float* Kc1  = (const float*)d_in[11];
    const float* bc1  = (const float*)d_in[12];
    const float* Kg2  = (const float*)d_in[13];
    const float* bg2  = (const float*)d_in[14];
    const float* Kc2  = (const float*)d_in[15];
    const float* bc2  = (const float*)d_in[16];
    float* out = (float*)d_out;

    decoder_kernel<<<GRID, TPB>>>(iv, emb, dW, db, decW,
                                  Kg0, bg0, Kc0, bc0,
                                  Kg1, bg1, Kc1, bc1,
                                  Kg2, bg2, Kc2, bc2, out);
}

// round 14
// speedup vs baseline: 1.7372x; 1.7372x over previous
#include <cuda_runtime.h>
#include <cstdint>

// ---------------- problem constants ----------------
#define BB 64
#define VOC 40
#define EMBD 32
#define L0N 512
#define L1N 1024
#define L2N 2048
#define NSUM (L0N + L1N + L2N)   // 3584
#define LATENT 512
#define STEPS 50
#define START_TOK 39
#define LOGITS_OFF (BB * STEPS)  // 3200

#define GRID 128
#define TPB  512
#define KBLK 64
#define XPAD 65   // smem row stride (uint64 units)

// ---------------- persistent device state (no allocation allowed) ----------------
__device__ float g_h0[BB * L0N];
__device__ float g_h1[BB * L1N];
__device__ float g_h2[BB * L2N];
__device__ float g_n0[BB * L0N];
__device__ float g_n1[BB * L1N];
__device__ float g_n2[BB * L2N];
__device__ float g_x[BB * EMBD];
__device__ int   g_done[BB];
__device__ uint64_t g_scrA[1 << 20];   // 8MB gates/dense split-K partials (col-pairs)
__device__ uint64_t g_scrB[1 << 20];   // 8MB cand split-K partials

// grid barrier state (monotonic generation; safe across graph replays) — R4-proven
__device__ unsigned          g_barcnt = 0;
__device__ volatile unsigned g_bargen = 0;

// ---------------- helpers ----------------
__device__ __forceinline__ void ffma2(uint64_t& d, uint64_t a, uint64_t b) {
    asm("fma.rn.f32x2 %0, %1, %2, %0;" : "+l"(d) : "l"(a), "l"(b));
}
__device__ __forceinline__ uint64_t pack2(float lo, float hi) {
    uint64_t r;
    asm("mov.b64 %0, {%1, %2};" : "=l"(r) : "f"(lo), "f"(hi));
    return r;
}
__device__ __forceinline__ void unpack2(uint64_t v, float& lo, float& hi) {
    asm("mov.b64 {%0, %1}, %2;" : "=f"(lo), "=f"(hi) : "l"(v));
}
__device__ __forceinline__ float sigmoidf_(float x) {
    return 1.0f / (1.0f + expf(-x));
}

// all 128 blocks are co-resident (GRID < 148 SMs) -> spin barrier is safe
__device__ __forceinline__ void grid_bar() {
    __syncthreads();
    if (threadIdx.x == 0) {
        unsigned gen = g_bargen;
        __threadfence();
        if (atomicAdd(&g_barcnt, 1u) == GRID - 1) {
            g_barcnt = 0;
            __threadfence();
            g_bargen = gen + 1;
        } else {
            while (g_bargen == gen) { }
            __threadfence();
        }
    }
    __syncthreads();
}

// ---------------- split-K GEMM phase (R4-exact inner loop) ----------------
// Block tile: 256 cols x 64 rows, K-chunked. Thread: 8 cols (4 pairs) x 4 rows.
// Partials -> scr[chunk][row][colpair].
// MODE 0: input = concat[x, h]                       (gates / dense)
// MODE 2: input = concat[x, r*h],
//         r = sigmoid(sum_ch scrA[ch][row][q] + bg[q])  (cand; gates reduce folded in)
template<int IN, int OUT, int NCOL, int TILES, int CHUNKS, int MODE, int CG>
__device__ __forceinline__ void gemm_phase(
    const float* __restrict__ W,
    const float* __restrict__ xbuf,
    const float* __restrict__ hbuf,
    const float* __restrict__ bg,      // MODE 2: gates bias
    uint64_t* __restrict__ scr,        // output scratch (A for gates/dense, B for cand)
    uint64_t* __restrict__ s_x2)       // smem: KBLK * XPAD uint64
{
    constexpr int KTOT = IN + OUT;
    constexpr int KC   = (KTOT + CHUNKS - 1) / CHUNKS;

    const int bid = blockIdx.x;
    if (bid < TILES * CHUNKS) {
        const int tile  = bid % TILES;
        const int chunk = bid / TILES;
        const int k0 = chunk * KC;
        const int k1 = (k0 + KC < KTOT) ? (k0 + KC) : KTOT;
        const int jbase = tile * 256;
        const int tid = threadIdx.x;
        const int c  = tid & 31;   // col-thread: 8 cols
        const int rg = tid >> 5;   // row-group: 4 rows

        uint64_t acc[4][4];
#pragma unroll
        for (int cp = 0; cp < 4; cp++)
#pragma unroll
            for (int r = 0; r < 4; r++) acc[cp][r] = 0ull;

        const float* Wc = W + jbase + c * 8;

        for (int kb = k0; kb < k1; kb += KBLK) {
            const int kt = (k1 - kb < KBLK) ? (k1 - kb) : KBLK;
            __syncthreads();
            // stage inputs: lanes stride over k (coalesced gmem), duplicated pair in smem
            for (int idx = tid; idx < 64 * KBLK; idx += TPB) {
                const int kk  = idx & (KBLK - 1);
                const int row = idx >> 6;
                if (kk < kt) {
                    const int kg = kb + kk;
                    float val;
                    if (kg < IN) {
                        val = xbuf[row * IN + kg];
                    } else {
                        const int q = kg - IN;
                        const float hv = hbuf[row * OUT + q];
                        if (MODE == 2) {
                            // fold gates reduction: r = sigmoid(sum of chunk partials + bias)
                            float s = bg[q];
#pragma unroll
                            for (int ch = 0; ch < CG; ch++) {
                                float a, b;
                                unpack2(g_scrA[(size_t)(ch * 64 + row) * OUT + (q >> 1)], a, b);
                                s += (q & 1) ? b : a;
                            }
                            val = sigmoidf_(s) * hv;
                        } else {
                            val = hv;
                        }
                    }
                    s_x2[kk * XPAD + row] = pack2(val, val);
                }
            }
            __syncthreads();

            const float* wrow = Wc + (size_t)kb * NCOL;
#pragma unroll 4
            for (int kk = 0; kk < kt; kk++) {
                const ulonglong2* wp = reinterpret_cast<const ulonglong2*>(wrow);
                const ulonglong2 wa  = wp[0];
                const ulonglong2 wb2 = wp[1];
                const uint64_t* xr = s_x2 + kk * XPAD + (rg << 2);
#pragma unroll
                for (int r = 0; r < 4; r++) {
                    const uint64_t xd = xr[r];
                    ffma2(acc[0][r], wa.x,  xd);
                    ffma2(acc[1][r], wa.y,  xd);
                    ffma2(acc[2][r], wb2.x, xd);
                    ffma2(acc[3][r], wb2.y, xd);
                }
                wrow += NCOL;
            }
        }

        // epilogue: partials to scratch (uint64 = col-pair), coalesced
#pragma unroll
        for (int r = 0; r < 4; r++) {
            const int row = (rg << 2) + r;
            uint64_t* dst = scr + (size_t)(chunk * 64 + row) * (NCOL / 2)
                                + (jbase >> 1) + (c << 2);
#pragma unroll
            for (int cp = 0; cp < 4; cp++) dst[cp] = acc[cp][r];
        }
    }
    grid_bar();
}

// ---------------- reduce + activation phases ----------------
// reduce_cand: n = z*h + (1-z)*tanh(cand_sum + bc),
// where z = sigmoid(gates_z_sum + bg[OUT+j]) is folded from gates scratch.
template<int OUT, int CHUNKS, int CG>
__device__ __forceinline__ void reduce_cand(const float* __restrict__ bc,
                                            const float* __restrict__ bg,
                                            const float* __restrict__ h,
                                            float* __restrict__ n)
{
    constexpr int HP = OUT / 2;
    const int NP = 64 * HP;
    for (int p = blockIdx.x * TPB + threadIdx.x; p < NP; p += GRID * TPB) {
        const int row = p / HP;
        const int jp  = p - row * HP;
        float s0 = 0.f, s1 = 0.f;
#pragma unroll 8
        for (int ch = 0; ch < CHUNKS; ch++) {
            float a, b;
            unpack2(g_scrB[(size_t)(ch * 64 + row) * HP + jp], a, b);
            s0 += a; s1 += b;
        }
        float zs0 = 0.f, zs1 = 0.f;
#pragma unroll
        for (int ch = 0; ch < CG; ch++) {
            float a, b;
            unpack2(g_scrA[(size_t)(ch * 64 + row) * OUT + HP + jp], a, b);
            zs0 += a; zs1 += b;
        }
        const int j = jp * 2;
        const float z0 = sigmoidf_(zs0 + bg[OUT + j]);
        const float z1 = sigmoidf_(zs1 + bg[OUT + j + 1]);
        const float c0 = tanhf(s0 + bc[j]);
        const float c1 = tanhf(s1 + bc[j + 1]);
        const float h0 = h[row * OUT + j];
        const float h1 = h[row * OUT + j + 1];
        n[row * OUT + j]     = z0 * h0 + (1.0f - z0) * c0;
        n[row * OUT + j + 1] = z1 * h1 + (1.0f - z1) * c1;
    }
    grid_bar();
}

__device__ __forceinline__ void reduce_dense(const float* __restrict__ db)
{
    constexpr int HP = NSUM / 2;   // 1792
    const int NP = 64 * HP;
    for (int p = blockIdx.x * TPB + threadIdx.x; p < NP; p += GRID * TPB) {
        const int row = p / HP;
        const int jp  = p - row * HP;
        float s0 = 0.f, s1 = 0.f;
#pragma unroll
        for (int ch = 0; ch < 8; ch++) {
            float a, b;
            unpack2(g_scrA[(size_t)(ch * 64 + row) * HP + jp], a, b);
            s0 += a; s1 += b;
        }
        const int j = jp * 2;
        const float y0 = s0 + db[j];
        const float y1 = s1 + db[j + 1];
        if (j < L0N) {
            g_h0[row * L0N + j] = y0; g_h0[row * L0N + j + 1] = y1;
        } else if (j < L0N + L1N) {
            g_h1[row * L1N + (j - L0N)] = y0; g_h1[row * L1N + (j - L0N) + 1] = y1;
        } else {
            g_h2[row * L2N + (j - L0N - L1N)] = y0; g_h2[row * L2N + (j - L0N - L1N) + 1] = y1;
        }
    }
    grid_bar();
}

// ---------------- decode phase (R4-exact) ----------------
__device__ __forceinline__ void decode_phase(const float* __restrict__ decW,
                                             const float* __restrict__ emb,
                                             float* __restrict__ out, int step)
{
    if (blockIdx.x < BB) {
        __shared__ float s_logit[VOC];
        __shared__ int s_idx, s_d0;
        const int b    = blockIdx.x;
        const int tid  = threadIdx.x;
        const int w    = tid >> 5;      // 16 warps
        const int lane = tid & 31;

        if (w < 8) {   // 8 warps x 5 logit cols
            float acc[5];
#pragma unroll
            for (int jj = 0; jj < 5; jj++) acc[jj] = 0.0f;

            const float* n2row = g_n2 + b * L2N;
            for (int k = lane; k < L2N; k += 32) {
                const float xv = n2row[k];
                const float* wr = decW + k * VOC + w * 5;
#pragma unroll
                for (int jj = 0; jj < 5; jj++) acc[jj] += xv * wr[jj];
            }
#pragma unroll
            for (int jj = 0; jj < 5; jj++) {
                float s = acc[jj];
#pragma unroll
                for (int off = 16; off > 0; off >>= 1)
                    s += __shfl_down_sync(0xffffffffu, s, off);
                if (lane == 0) s_logit[w * 5 + jj] = s;
            }
        }
        __syncthreads();

        if (tid == 0) {
            const int d0 = g_done[b];
            float best = s_logit[0];
            int bi = 0;
            for (int jj = 1; jj < VOC; jj++) {
                const float lv = s_logit[jj];
                if (lv > best) { best = lv; bi = jj; }   // first-max on ties
            }
            s_idx = bi;
            s_d0  = d0;
            out[b * STEPS + step] = (float)(d0 ? 0 : bi);   // STOP_TOK == 0
            g_done[b] = d0 | (bi == 0);
        }
        __syncthreads();

        const int d0  = s_d0;
        const int idx = s_idx;

        float* lo = out + LOGITS_OFF + (b * STEPS + step) * VOC;
        for (int jj = tid; jj < VOC; jj += TPB)
            lo[jj] = d0 ? 0.0f : s_logit[jj];

        if (!d0) {
            for (int q = tid; q < L0N; q += TPB) g_h0[b * L0N + q] = g_n0[b * L0N + q];
            for (int q = tid; q < L1N; q += TPB) g_h1[b * L1N + q] = g_n1[b * L1N + q];
            for (int q = tid; q < L2N; q += TPB) g_h2[b * L2N + q] = g_n2[b * L2N + q];
            if (tid < EMBD) g_x[b * EMBD + tid] = emb[idx * EMBD + tid];
        }
    }
    grid_bar();
}

// ---------------- the single persistent kernel ----------------
__global__ void __launch_bounds__(TPB, 1) decoder_kernel(
    const float* __restrict__ iv,   const float* __restrict__ emb,
    const float* __restrict__ dW,   const float* __restrict__ db,
    const float* __restrict__ decW,
    const float* __restrict__ Kg0, const float* __restrict__ bg0,
    const float* __restrict__ Kc0, const float* __restrict__ bc0,
    const float* __restrict__ Kg1, const float* __restrict__ bg1,
    const float* __restrict__ Kc1, const float* __restrict__ bc1,
    const float* __restrict__ Kg2, const float* __restrict__ bg2,
    const float* __restrict__ Kc2, const float* __restrict__ bc2,
    float* __restrict__ out)
{
    __shared__ __align__(16) uint64_t s_x2[KBLK * XPAD];

    // init x / done (blocks 112..127 idle during the 112-block dense gemm)
    if (blockIdx.x == 112) {
        for (int i = threadIdx.x; i < BB * EMBD; i += TPB)
            g_x[i] = emb[START_TOK * EMBD + (i & (EMBD - 1))];
        if (threadIdx.x < BB) g_done[threadIdx.x] = 0;
    }

    // initial hidden states: y = iv @ dense_W + dense_b
    gemm_phase<LATENT, 0, NSUM, 14, 8, 0, 0>(dW, iv, nullptr, nullptr, g_scrA, s_x2);
    reduce_dense(db);

    for (int s = 0; s < STEPS; s++) {
        // layer 0: gates -> scrA; cand (r folded from scrA) -> scrB; combine (z folded)
        gemm_phase<EMBD, L0N, 2 * L0N, 4, 32, 0, 0 >(Kg0, g_x,  g_h0, nullptr, g_scrA, s_x2);
        gemm_phase<EMBD, L0N, L0N,     2, 64, 2, 32>(Kc0, g_x,  g_h0, bg0,     g_scrB, s_x2);
        reduce_cand<L0N, 64, 32>(bc0, bg0, g_h0, g_n0);

        // layer 1
        gemm_phase<L0N,  L1N, 2 * L1N, 8, 16, 0, 0 >(Kg1, g_n0, g_h1, nullptr, g_scrA, s_x2);
        gemm_phase<L0N,  L1N, L1N,     4, 32, 2, 16>(Kc1, g_n0, g_h1, bg1,     g_scrB, s_x2);
        reduce_cand<L1N, 32, 16>(bc1, bg1, g_h1, g_n1);

        // layer 2
        gemm_phase<L1N,  L2N, 2 * L2N, 16, 8, 0, 0 >(Kg2, g_n1, g_h2, nullptr, g_scrA, s_x2);
        gemm_phase<L1N,  L2N, L2N,     8, 16, 2, 8 >(Kc2, g_n1, g_h2, bg2,     g_scrB, s_x2);
        reduce_cand<L2N, 16, 8>(bc2, bg2, g_h2, g_n2);

        decode_phase(decW, emb, out, s);
    }
}

// ---------------- launch ----------------
extern "C" void kernel_launch(void* const* d_in, const int* in_sizes, int n_in,
                              void* d_out, int out_size)
{
    const float* iv   = (const float*)d_in[0];
    const float* emb  = (const float*)d_in[1];
    const float* dW   = (const float*)d_in[2];
    const float* db   = (const float*)d_in[3];
    const float* decW = (const float*)d_in[4];
    const float* Kg0  = (const float*)d_in[5];
    const float* bg0  = (const float*)d_in[6];
    const float* Kc0  = (const float*)d_in[7];
    const float* bc0  = (const float*)d_in[8];
    const float* Kg1  = (const float*)d_in[9];
    const float* bg1  = (const float*)d_in[10];
    const float* Kc1  = (const float*)d_in[11];
    const float* bc1  = (const float*)d_in[12];
    const float* Kg2  = (const float*)d_in[13];
    const float* bg2  = (const float*)d_in[14];
    const float* Kc2  = (const float*)d_in[15];
    const float* bc2  = (const float*)d_in[16];
    float* out = (float*)d_out;

    decoder_kernel<<<GRID, TPB>>>(iv, emb, dW, db, decW,
                                  Kg0, bg0, Kc0, bc0,
                                  Kg1, bg1, Kc1, bc1,
                                  Kg2, bg2, Kc2, bc2, out);
}

// round 15
// speedup vs baseline: 2.1498x; 1.2375x over previous
#include <cuda_runtime.h>
#include <cstdint>

// ---------------- problem constants ----------------
#define BB 64
#define VOC 40
#define EMBD 32
#define L0N 512
#define L1N 1024
#define L2N 2048
#define NSUM (L0N + L1N + L2N)   // 3584
#define LATENT 512
#define STEPS 50
#define START_TOK 39
#define LOGITS_OFF (BB * STEPS)  // 3200

#define GRID 128
#define TPB  512
#define KBLK 64
#define XPAD 65   // smem row stride (uint64 units)

// ---------------- persistent device state (no allocation allowed) ----------------
__device__ float g_h0[BB * L0N];
__device__ float g_h1[BB * L1N];
__device__ float g_h2[BB * L2N];
__device__ float g_n0[BB * L0N];
__device__ float g_n1[BB * L1N];
__device__ float g_n2[BB * L2N];
__device__ float g_v0[BB * 2 * L0N];
__device__ float g_v1[BB * 2 * L1N];
__device__ float g_v2[BB * 2 * L2N];
__device__ float g_x[BB * EMBD];
__device__ int   g_done[BB];
__device__ float g_scr[2 << 20];            // 8MB split-K partial sums

// grid barrier state (monotonic generation; safe across graph replays) — proven
__device__ unsigned          g_barcnt = 0;
__device__ volatile unsigned g_bargen = 0;

// ---------------- helpers ----------------
__device__ __forceinline__ void ffma2(uint64_t& d, uint64_t a, uint64_t b) {
    asm("fma.rn.f32x2 %0, %1, %2, %0;" : "+l"(d) : "l"(a), "l"(b));
}
__device__ __forceinline__ uint64_t pack2(float lo, float hi) {
    uint64_t r;
    asm("mov.b64 %0, {%1, %2};" : "=l"(r) : "f"(lo), "f"(hi));
    return r;
}
__device__ __forceinline__ void unpack2(uint64_t v, float& lo, float& hi) {
    asm("mov.b64 {%0, %1}, %2;" : "=f"(lo), "=f"(hi) : "l"(v));
}
__device__ __forceinline__ float sigmoidf_(float x) {
    return 1.0f / (1.0f + expf(-x));
}

// all 128 blocks are co-resident (GRID < 148 SMs) -> spin barrier is safe
__device__ __forceinline__ void grid_bar() {
    __syncthreads();
    if (threadIdx.x == 0) {
        unsigned gen = g_bargen;
        __threadfence();
        if (atomicAdd(&g_barcnt, 1u) == GRID - 1) {
            g_barcnt = 0;
            __threadfence();
            g_bargen = gen + 1;
        } else {
            while (g_bargen == gen) { }
            __threadfence();
        }
    }
    __syncthreads();
}

// ---------------- split-K GEMM phase (R4-exact; scratch stores are evict-first) ----------------
// Block tile: 256 cols x 64 rows, K-chunked. Thread: 8 cols (4 pairs) x 4 rows.
// Partials -> g_scr[chunk][row][colpair] via __stcs (streaming, don't evict weights).
// MODE 0: input = concat[x, h];  MODE 1: input = concat[x, r*h] (r = 1st half of v)
template<int IN, int OUT, int NCOL, int TILES, int CHUNKS, int MODE>
__device__ __forceinline__ void gemm_phase(
    const float* __restrict__ W,
    const float* __restrict__ xbuf,
    const float* __restrict__ hbuf,
    const float* __restrict__ vbuf,
    uint64_t* __restrict__ s_x2)   // smem: KBLK * XPAD uint64
{
    constexpr int KTOT = IN + OUT;
    constexpr int KC   = (KTOT + CHUNKS - 1) / CHUNKS;

    const int bid = blockIdx.x;
    if (bid < TILES * CHUNKS) {
        const int tile  = bid % TILES;
        const int chunk = bid / TILES;
        const int k0 = chunk * KC;
        const int k1 = (k0 + KC < KTOT) ? (k0 + KC) : KTOT;
        const int jbase = tile * 256;
        const int tid = threadIdx.x;
        const int c  = tid & 31;   // col-thread: 8 cols
        const int rg = tid >> 5;   // row-group: 4 rows

        uint64_t acc[4][4];
#pragma unroll
        for (int cp = 0; cp < 4; cp++)
#pragma unroll
            for (int r = 0; r < 4; r++) acc[cp][r] = 0ull;

        const float* Wc = W + jbase + c * 8;

        for (int kb = k0; kb < k1; kb += KBLK) {
            const int kt = (k1 - kb < KBLK) ? (k1 - kb) : KBLK;
            __syncthreads();
            // stage inputs: lanes stride over k (coalesced gmem), duplicated pair in smem
            for (int idx = tid; idx < 64 * KBLK; idx += TPB) {
                const int kk  = idx & (KBLK - 1);
                const int row = idx >> 6;
                if (kk < kt) {
                    const int kg = kb + kk;
                    float val;
                    if (kg < IN) {
                        val = xbuf[row * IN + kg];
                    } else {
                        const int q = kg - IN;
                        const float hv = hbuf[row * OUT + q];
                        if (MODE == 1)
                            val = vbuf[row * (2 * OUT) + q] * hv;
                        else
                            val = hv;
                    }
                    s_x2[kk * XPAD + row] = pack2(val, val);
                }
            }
            __syncthreads();

            const float* wrow = Wc + (size_t)kb * NCOL;
#pragma unroll 4
            for (int kk = 0; kk < kt; kk++) {
                const ulonglong2* wp = reinterpret_cast<const ulonglong2*>(wrow);
                const ulonglong2 wa  = wp[0];
                const ulonglong2 wb2 = wp[1];
                const uint64_t* xr = s_x2 + kk * XPAD + (rg << 2);
#pragma unroll
                for (int r = 0; r < 4; r++) {
                    const uint64_t xd = xr[r];
                    ffma2(acc[0][r], wa.x,  xd);
                    ffma2(acc[1][r], wa.y,  xd);
                    ffma2(acc[2][r], wb2.x, xd);
                    ffma2(acc[3][r], wb2.y, xd);
                }
                wrow += NCOL;
            }
        }

        // epilogue: partials to scratch (uint64 = col-pair), streaming stores (evict-first)
        unsigned long long* scr = reinterpret_cast<unsigned long long*>(g_scr);
#pragma unroll
        for (int r = 0; r < 4; r++) {
            const int row = (rg << 2) + r;
            unsigned long long* dst = scr + (size_t)(chunk * 64 + row) * (NCOL / 2)
                                          + (jbase >> 1) + (c << 2);
#pragma unroll
            for (int cp = 0; cp < 4; cp++)
                __stcs(dst + cp, (unsigned long long)acc[cp][r]);
        }
    }
    grid_bar();
}

// ---------------- reduce + activation phases (streaming scratch reads) ----------------
template<int OUT, int CHUNKS>
__device__ __forceinline__ void reduce_gates(const float* __restrict__ bg,
                                             float* __restrict__ v)
{
    const int NP = 64 * OUT;   // col-pairs (NCOL/2 = OUT)
    const unsigned long long* scr = reinterpret_cast<const unsigned long long*>(g_scr);
    for (int p = blockIdx.x * TPB + threadIdx.x; p < NP; p += GRID * TPB) {
        const int row = p / OUT;
        const int jp  = p - row * OUT;
        float s0 = 0.f, s1 = 0.f;
#pragma unroll 8
        for (int ch = 0; ch < CHUNKS; ch++) {
            float a, b;
            unpack2((uint64_t)__ldcs(scr + (size_t)(ch * 64 + row) * OUT + jp), a, b);
            s0 += a; s1 += b;
        }
        const int j = jp * 2;
        v[row * (2 * OUT) + j]     = sigmoidf_(s0 + bg[j]);
        v[row * (2 * OUT) + j + 1] = sigmoidf_(s1 + bg[j + 1]);
    }
    grid_bar();
}

template<int OUT, int CHUNKS>
__device__ __forceinline__ void reduce_cand(const float* __restrict__ bc,
                                            const float* __restrict__ v,
                                            const float* __restrict__ h,
                                            float* __restrict__ n)
{
    constexpr int HP = OUT / 2;
    const int NP = 64 * HP;
    const unsigned long long* scr = reinterpret_cast<const unsigned long long*>(g_scr);
    for (int p = blockIdx.x * TPB + threadIdx.x; p < NP; p += GRID * TPB) {
        const int row = p / HP;
        const int jp  = p - row * HP;
        float s0 = 0.f, s1 = 0.f;
#pragma unroll 8
        for (int ch = 0; ch < CHUNKS; ch++) {
            float a, b;
            unpack2((uint64_t)__ldcs(scr + (size_t)(ch * 64 + row) * HP + jp), a, b);
            s0 += a; s1 += b;
        }
        const int j = jp * 2;
#pragma unroll
        for (int t = 0; t < 2; t++) {
            const float cv = tanhf(((t == 0) ? s0 : s1) + bc[j + t]);
            const float z  = v[row * (2 * OUT) + OUT + j + t];
            const float hv = h[row * OUT + j + t];
            n[row * OUT + j + t] = z * hv + (1.0f - z) * cv;
        }
    }
    grid_bar();
}

__device__ __forceinline__ void reduce_dense(const float* __restrict__ db)
{
    constexpr int HP = NSUM / 2;   // 1792
    const int NP = 64 * HP;
    const unsigned long long* scr = reinterpret_cast<const unsigned long long*>(g_scr);
    for (int p = blockIdx.x * TPB + threadIdx.x; p < NP; p += GRID * TPB) {
        const int row = p / HP;
        const int jp  = p - row * HP;
        float s0 = 0.f, s1 = 0.f;
#pragma unroll
        for (int ch = 0; ch < 8; ch++) {
            float a, b;
            unpack2((uint64_t)__ldcs(scr + (size_t)(ch * 64 + row) * HP + jp), a, b);
            s0 += a; s1 += b;
        }
        const int j = jp * 2;
        const float y0 = s0 + db[j];
        const float y1 = s1 + db[j + 1];
        if (j < L0N) {
            g_h0[row * L0N + j] = y0; g_h0[row * L0N + j + 1] = y1;
        } else if (j < L0N + L1N) {
            g_h1[row * L1N + (j - L0N)] = y0; g_h1[row * L1N + (j - L0N) + 1] = y1;
        } else {
            g_h2[row * L2N + (j - L0N - L1N)] = y0; g_h2[row * L2N + (j - L0N - L1N) + 1] = y1;
        }
    }
    grid_bar();
}

// ---------------- decode phase (R4-exact) ----------------
__device__ __forceinline__ void decode_phase(const float* __restrict__ decW,
                                             const float* __restrict__ emb,
                                             float* __restrict__ out, int step)
{
    if (blockIdx.x < BB) {
        __shared__ float s_logit[VOC];
        __shared__ int s_idx, s_d0;
        const int b    = blockIdx.x;
        const int tid  = threadIdx.x;
        const int w    = tid >> 5;      // 16 warps
        const int lane = tid & 31;

        if (w < 8) {   // 8 warps x 5 logit cols
            float acc[5];
#pragma unroll
            for (int jj = 0; jj < 5; jj++) acc[jj] = 0.0f;

            const float* n2row = g_n2 + b * L2N;
            for (int k = lane; k < L2N; k += 32) {
                const float xv = n2row[k];
                const float* wr = decW + k * VOC + w * 5;
#pragma unroll
                for (int jj = 0; jj < 5; jj++) acc[jj] += xv * wr[jj];
            }
#pragma unroll
            for (int jj = 0; jj < 5; jj++) {
                float s = acc[jj];
#pragma unroll
                for (int off = 16; off > 0; off >>= 1)
                    s += __shfl_down_sync(0xffffffffu, s, off);
                if (lane == 0) s_logit[w * 5 + jj] = s;
            }
        }
        __syncthreads();

        if (tid == 0) {
            const int d0 = g_done[b];
            float best = s_logit[0];
            int bi = 0;
            for (int jj = 1; jj < VOC; jj++) {
                const float lv = s_logit[jj];
                if (lv > best) { best = lv; bi = jj; }   // first-max on ties
            }
            s_idx = bi;
            s_d0  = d0;
            out[b * STEPS + step] = (float)(d0 ? 0 : bi);   // STOP_TOK == 0
            g_done[b] = d0 | (bi == 0);
        }
        __syncthreads();

        const int d0  = s_d0;
        const int idx = s_idx;

        float* lo = out + LOGITS_OFF + (b * STEPS + step) * VOC;
        for (int jj = tid; jj < VOC; jj += TPB)
            lo[jj] = d0 ? 0.0f : s_logit[jj];

        if (!d0) {
            for (int q = tid; q < L0N; q += TPB) g_h0[b * L0N + q] = g_n0[b * L0N + q];
            for (int q = tid; q < L1N; q += TPB) g_h1[b * L1N + q] = g_n1[b * L1N + q];
            for (int q = tid; q < L2N; q += TPB) g_h2[b * L2N + q] = g_n2[b * L2N + q];
            if (tid < EMBD) g_x[b * EMBD + tid] = emb[idx * EMBD + tid];
        }
    }
    grid_bar();
}

// ---------------- the single persistent kernel ----------------
__global__ void __launch_bounds__(TPB, 1) decoder_kernel(
    const float* __restrict__ iv,   const float* __restrict__ emb,
    const float* __restrict__ dW,   const float* __restrict__ db,
    const float* __restrict__ decW,
    const float* __restrict__ Kg0, const float* __restrict__ bg0,
    const float* __restrict__ Kc0, const float* __restrict__ bc0,
    const float* __restrict__ Kg1, const float* __restrict__ bg1,
    const float* __restrict__ Kc1, const float* __restrict__ bc1,
    const float* __restrict__ Kg2, const float* __restrict__ bg2,
    const float* __restrict__ Kc2, const float* __restrict__ bc2,
    float* __restrict__ out)
{
    __shared__ __align__(16) uint64_t s_x2[KBLK * XPAD];

    // init x / done (blocks 112..127 idle during the 112-block dense gemm)
    if (blockIdx.x == 112) {
        for (int i = threadIdx.x; i < BB * EMBD; i += TPB)
            g_x[i] = emb[START_TOK * EMBD + (i & (EMBD - 1))];
        if (threadIdx.x < BB) g_done[threadIdx.x] = 0;
    }

    // initial hidden states: y = iv @ dense_W + dense_b
    gemm_phase<LATENT, 0, NSUM, 14, 8, 0>(dW, iv, nullptr, nullptr, s_x2);
    reduce_dense(db);

    for (int s = 0; s < STEPS; s++) {
        gemm_phase<EMBD, L0N, 2 * L0N, 4, 32, 0>(Kg0, g_x,  g_h0, nullptr, s_x2);
        reduce_gates<L0N, 32>(bg0, g_v0);
        gemm_phase<EMBD, L0N, L0N,     2, 64, 1>(Kc0, g_x,  g_h0, g_v0,   s_x2);
        reduce_cand<L0N, 64>(bc0, g_v0, g_h0, g_n0);

        gemm_phase<L0N,  L1N, 2 * L1N, 8, 16, 0>(Kg1, g_n0, g_h1, nullptr, s_x2);
        reduce_gates<L1N, 16>(bg1, g_v1);
        gemm_phase<L0N,  L1N, L1N,     4, 32, 1>(Kc1, g_n0, g_h1, g_v1,   s_x2);
        reduce_cand<L1N, 32>(bc1, g_v1, g_h1, g_n1);

        gemm_phase<L1N,  L2N, 2 * L2N, 16, 8, 0>(Kg2, g_n1, g_h2, nullptr, s_x2);
        reduce_gates<L2N, 8>(bg2, g_v2);
        gemm_phase<L1N,  L2N, L2N,     8, 16, 1>(Kc2, g_n1, g_h2, g_v2,   s_x2);
        reduce_cand<L2N, 16>(bc2, g_v2, g_h2, g_n2);

        decode_phase(decW, emb, out, s);
    }
}

// ---------------- launch ----------------
extern "C" void kernel_launch(void* const* d_in, const int* in_sizes, int n_in,
                              void* d_out, int out_size)
{
    const float* iv   = (const float*)d_in[0];
    const float* emb  = (const float*)d_in[1];
    const float* dW   = (const float*)d_in[2];
    const float* db   = (const float*)d_in[3];
    const float* decW = (const float*)d_in[4];
    const float* Kg0  = (const float*)d_in[5];
    const float* bg0  = (const float*)d_in[6];
    const float* Kc0  = (const float*)d_in[7];
    const float* bc0  = (const float*)d_in[8];
    const float* Kg1  = (const float*)d_in[9];
    const float* bg1  = (const float*)d_in[10];
    const float* Kc1  = (const float*)d_in[11];
    const float* bc1  = (const float*)d_in[12];
    const float* Kg2  = (const float*)d_in[13];
    const float* bg2  = (const float*)d_in[14];
    const float* Kc2  = (const float*)d_in[15];
    const float* bc2  = (const float*)d_in[16];
    float* out = (float*)d_out;

    decoder_kernel<<<GRID, TPB>>>(iv, emb, dW, db, decW,
                                  Kg0, bg0, Kc0, bc0,
                                  Kg1, bg1, Kc1, bc1,
                                  Kg2, bg2, Kc2, bc2, out);
}

// round 16
// speedup vs baseline: 2.2018x; 1.0242x over previous
#include <cuda_runtime.h>
#include <cstdint>

// ---------------- problem constants ----------------
#define BB 64
#define VOC 40
#define EMBD 32
#define L0N 512
#define L1N 1024
#define L2N 2048
#define NSUM (L0N + L1N + L2N)   // 3584
#define LATENT 512
#define STEPS 50
#define START_TOK 39
#define LOGITS_OFF (BB * STEPS)  // 3200

#define GRID 128
#define TPB  512
#define KBLK 64
#define SEG  4
#define XPAD 65   // smem row stride (uint64 units)

// ---------------- persistent device state (no allocation allowed) ----------------
__device__ float g_h0[BB * L0N];
__device__ float g_h1[BB * L1N];
__device__ float g_h2[BB * L2N];
__device__ float g_n0[BB * L0N];
__device__ float g_n1[BB * L1N];
__device__ float g_n2[BB * L2N];
__device__ float g_v0[BB * 2 * L0N];
__device__ float g_v1[BB * 2 * L1N];
__device__ float g_v2[BB * 2 * L2N];
__device__ float g_x[BB * EMBD];
__device__ int   g_done[BB];
__device__ float g_scr[2 << 20];            // 8MB split-K partial sums

// grid barrier state (monotonic generation; safe across graph replays) — proven
__device__ unsigned          g_barcnt = 0;
__device__ volatile unsigned g_bargen = 0;

// ---------------- helpers ----------------
__device__ __forceinline__ void ffma2(uint64_t& d, uint64_t a, uint64_t b) {
    asm("fma.rn.f32x2 %0, %1, %2, %0;" : "+l"(d) : "l"(a), "l"(b));
}
__device__ __forceinline__ uint64_t pack2(float lo, float hi) {
    uint64_t r;
    asm("mov.b64 %0, {%1, %2};" : "=l"(r) : "f"(lo), "f"(hi));
    return r;
}
__device__ __forceinline__ void unpack2(uint64_t v, float& lo, float& hi) {
    asm("mov.b64 {%0, %1}, %2;" : "=f"(lo), "=f"(hi) : "l"(v));
}
__device__ __forceinline__ float sigmoidf_(float x) {
    return 1.0f / (1.0f + expf(-x));
}

// all 128 blocks are co-resident (GRID < 148 SMs) -> spin barrier is safe
__device__ __forceinline__ void grid_bar() {
    __syncthreads();
    if (threadIdx.x == 0) {
        unsigned gen = g_bargen;
        __threadfence();
        if (atomicAdd(&g_barcnt, 1u) == GRID - 1) {
            g_barcnt = 0;
            __threadfence();
            g_bargen = gen + 1;
        } else {
            while (g_bargen == gen) { }
            __threadfence();
        }
    }
    __syncthreads();
}

// ---------------- split-K GEMM phase (R4 dataflow; burst-loaded inner loop) ----------------
// Block tile: 256 cols x 64 rows, K-chunked. Thread: 8 cols (4 pairs) x 4 rows.
// Inner loop: segments of SEG=4 k's. Per segment: 8 unconditional LDG.128 (burst,
// high MLP to saturate DRAM), then 64 FFMA2 from registers. Ragged k handled by
// zero-padded x staging + clamped weight row (x=0 => contributes nothing).
// Partials -> g_scr[chunk][row][colpair].
// MODE 0: input = concat[x, h];  MODE 1: input = concat[x, r*h] (r = 1st half of v)
template<int IN, int OUT, int NCOL, int TILES, int CHUNKS, int MODE>
__device__ __forceinline__ void gemm_phase(
    const float* __restrict__ W,
    const float* __restrict__ xbuf,
    const float* __restrict__ hbuf,
    const float* __restrict__ vbuf,
    uint64_t* __restrict__ s_x2)   // smem: KBLK * XPAD uint64
{
    constexpr int KTOT = IN + OUT;
    constexpr int KC   = (KTOT + CHUNKS - 1) / CHUNKS;

    const int bid = blockIdx.x;
    if (bid < TILES * CHUNKS) {
        const int tile  = bid % TILES;
        const int chunk = bid / TILES;
        const int k0 = chunk * KC;
        const int k1 = (k0 + KC < KTOT) ? (k0 + KC) : KTOT;
        const int jbase = tile * 256;
        const int tid = threadIdx.x;
        const int c  = tid & 31;   // col-thread: 8 cols
        const int rg = tid >> 5;   // row-group: 4 rows

        uint64_t acc[4][4];
#pragma unroll
        for (int cp = 0; cp < 4; cp++)
#pragma unroll
            for (int r = 0; r < 4; r++) acc[cp][r] = 0ull;

        const float* Wc = W + jbase + c * 8;

        for (int kb = k0; kb < k1; kb += KBLK) {
            const int kt  = (k1 - kb < KBLK) ? (k1 - kb) : KBLK;
            const int ktp = (kt + SEG - 1) & ~(SEG - 1);   // pad to segment multiple
            __syncthreads();
            // stage inputs: duplicated (v,v) pairs; zero-fill padded slots [kt, ktp)
            for (int idx = tid; idx < 64 * KBLK; idx += TPB) {
                const int kk  = idx & (KBLK - 1);
                const int row = idx >> 6;
                if (kk < kt) {
                    const int kg = kb + kk;
                    float val;
                    if (kg < IN) {
                        val = xbuf[row * IN + kg];
                    } else {
                        const int q = kg - IN;
                        const float hv = hbuf[row * OUT + q];
                        if (MODE == 1)
                            val = vbuf[row * (2 * OUT) + q] * hv;
                        else
                            val = hv;
                    }
                    s_x2[kk * XPAD + row] = pack2(val, val);
                } else if (kk < ktp) {
                    s_x2[kk * XPAD + row] = 0ull;   // padded k contributes 0
                }
            }
            __syncthreads();

            for (int sg = 0; sg < ktp; sg += SEG) {
                // ---- load burst: 8 independent LDG.128, no guards ----
                ulonglong2 wa[SEG], wb[SEG];
#pragma unroll
                for (int i = 0; i < SEG; i++) {
                    int kr = kb + sg + i;
                    kr = (kr < KTOT - 1) ? kr : (KTOT - 1);   // clamp (x is 0 there)
                    const float* wrow = Wc + (size_t)kr * NCOL;
                    wa[i] = *reinterpret_cast<const ulonglong2*>(wrow);
                    wb[i] = *reinterpret_cast<const ulonglong2*>(wrow + 4);
                }
                // ---- compute burst: SEG x 16 FFMA2 ----
#pragma unroll
                for (int i = 0; i < SEG; i++) {
                    const uint64_t* xr = s_x2 + (sg + i) * XPAD + (rg << 2);
#pragma unroll
                    for (int r = 0; r < 4; r++) {
                        const uint64_t xd = xr[r];
                        ffma2(acc[0][r], wa[i].x, xd);
                        ffma2(acc[1][r], wa[i].y, xd);
                        ffma2(acc[2][r], wb[i].x, xd);
                        ffma2(acc[3][r], wb[i].y, xd);
                    }
                }
            }
        }

        // epilogue: partials to scratch (uint64 = col-pair), coalesced
        uint64_t* scr = reinterpret_cast<uint64_t*>(g_scr);
#pragma unroll
        for (int r = 0; r < 4; r++) {
            const int row = (rg << 2) + r;
            uint64_t* dst = scr + (size_t)(chunk * 64 + row) * (NCOL / 2)
                                + (jbase >> 1) + (c << 2);
#pragma unroll
            for (int cp = 0; cp < 4; cp++) dst[cp] = acc[cp][r];
        }
    }
    grid_bar();
}

// ---------------- reduce + activation phases (R4-exact) ----------------
template<int OUT, int CHUNKS>
__device__ __forceinline__ void reduce_gates(const float* __restrict__ bg,
                                             float* __restrict__ v)
{
    const int NP = 64 * OUT;   // col-pairs (NCOL/2 = OUT)
    const uint64_t* scr = reinterpret_cast<const uint64_t*>(g_scr);
    for (int p = blockIdx.x * TPB + threadIdx.x; p < NP; p += GRID * TPB) {
        const int row = p / OUT;
        const int jp  = p - row * OUT;
        float s0 = 0.f, s1 = 0.f;
#pragma unroll 8
        for (int ch = 0; ch < CHUNKS; ch++) {
            float a, b;
            unpack2(scr[(size_t)(ch * 64 + row) * OUT + jp], a, b);
            s0 += a; s1 += b;
        }
        const int j = jp * 2;
        v[row * (2 * OUT) + j]     = sigmoidf_(s0 + bg[j]);
        v[row * (2 * OUT) + j + 1] = sigmoidf_(s1 + bg[j + 1]);
    }
    grid_bar();
}

template<int OUT, int CHUNKS>
__device__ __forceinline__ void reduce_cand(const float* __restrict__ bc,
                                            const float* __restrict__ v,
                                            const float* __restrict__ h,
                                            float* __restrict__ n)
{
    constexpr int HP = OUT / 2;
    const int NP = 64 * HP;
    const uint64_t* scr = reinterpret_cast<const uint64_t*>(g_scr);
    for (int p = blockIdx.x * TPB + threadIdx.x; p < NP; p += GRID * TPB) {
        const int row = p / HP;
        const int jp  = p - row * HP;
        float s0 = 0.f, s1 = 0.f;
#pragma unroll 8
        for (int ch = 0; ch < CHUNKS; ch++) {
            float a, b;
            unpack2(scr[(size_t)(ch * 64 + row) * HP + jp], a, b);
            s0 += a; s1 += b;
        }
        const int j = jp * 2;
#pragma unroll
        for (int t = 0; t < 2; t++) {
            const float cv = tanhf(((t == 0) ? s0 : s1) + bc[j + t]);
            const float z  = v[row * (2 * OUT) + OUT + j + t];
            const float hv = h[row * OUT + j + t];
            n[row * OUT + j + t] = z * hv + (1.0f - z) * cv;
        }
    }
    grid_bar();
}

__device__ __forceinline__ void reduce_dense(const float* __restrict__ db)
{
    constexpr int HP = NSUM / 2;   // 1792
    const int NP = 64 * HP;
    const uint64_t* scr = reinterpret_cast<const uint64_t*>(g_scr);
    for (int p = blockIdx.x * TPB + threadIdx.x; p < NP; p += GRID * TPB) {
        const int row = p / HP;
        const int jp  = p - row * HP;
        float s0 = 0.f, s1 = 0.f;
#pragma unroll
        for (int ch = 0; ch < 8; ch++) {
            float a, b;
            unpack2(scr[(size_t)(ch * 64 + row) * HP + jp], a, b);
            s0 += a; s1 += b;
        }
        const int j = jp * 2;
        const float y0 = s0 + db[j];
        const float y1 = s1 + db[j + 1];
        if (j < L0N) {
            g_h0[row * L0N + j] = y0; g_h0[row * L0N + j + 1] = y1;
        } else if (j < L0N + L1N) {
            g_h1[row * L1N + (j - L0N)] = y0; g_h1[row * L1N + (j - L0N) + 1] = y1;
        } else {
            g_h2[row * L2N + (j - L0N - L1N)] = y0; g_h2[row * L2N + (j - L0N - L1N) + 1] = y1;
        }
    }
    grid_bar();
}

// ---------------- decode phase (R4-exact) ----------------
__device__ __forceinline__ void decode_phase(const float* __restrict__ decW,
                                             const float* __restrict__ emb,
                                             float* __restrict__ out, int step)
{
    if (blockIdx.x < BB) {
        __shared__ float s_logit[VOC];
        __shared__ int s_idx, s_d0;
        const int b    = blockIdx.x;
        const int tid  = threadIdx.x;
        const int w    = tid >> 5;      // 16 warps
        const int lane = tid & 31;

        if (w < 8) {   // 8 warps x 5 logit cols
            float acc[5];
#pragma unroll
            for (int jj = 0; jj < 5; jj++) acc[jj] = 0.0f;

            const float* n2row = g_n2 + b * L2N;
            for (int k = lane; k < L2N; k += 32) {
                const float xv = n2row[k];
                const float* wr = decW + k * VOC + w * 5;
#pragma unroll
                for (int jj = 0; jj < 5; jj++) acc[jj] += xv * wr[jj];
            }
#pragma unroll
            for (int jj = 0; jj < 5; jj++) {
                float s = acc[jj];
#pragma unroll
                for (int off = 16; off > 0; off >>= 1)
                    s += __shfl_down_sync(0xffffffffu, s, off);
                if (lane == 0) s_logit[w * 5 + jj] = s;
            }
        }
        __syncthreads();

        if (tid == 0) {
            const int d0 = g_done[b];
            float best = s_logit[0];
            int bi = 0;
            for (int jj = 1; jj < VOC; jj++) {
                const float lv = s_logit[jj];
                if (lv > best) { best = lv; bi = jj; }   // first-max on ties
            }
            s_idx = bi;
            s_d0  = d0;
            out[b * STEPS + step] = (float)(d0 ? 0 : bi);   // STOP_TOK == 0
            g_done[b] = d0 | (bi == 0);
        }
        __syncthreads();

        const int d0  = s_d0;
        const int idx = s_idx;

        float* lo = out + LOGITS_OFF + (b * STEPS + step) * VOC;
        for (int jj = tid; jj < VOC; jj += TPB)
            lo[jj] = d0 ? 0.0f : s_logit[jj];

        if (!d0) {
            for (int q = tid; q < L0N; q += TPB) g_h0[b * L0N + q] = g_n0[b * L0N + q];
            for (int q = tid; q < L1N; q += TPB) g_h1[b * L1N + q] = g_n1[b * L1N + q];
            for (int q = tid; q < L2N; q += TPB) g_h2[b * L2N + q] = g_n2[b * L2N + q];
            if (tid < EMBD) g_x[b * EMBD + tid] = emb[idx * EMBD + tid];
        }
    }
    grid_bar();
}

// ---------------- the single persistent kernel ----------------
__global__ void __launch_bounds__(TPB, 1) decoder_kernel(
    const float* __restrict__ iv,   const float* __restrict__ emb,
    const float* __restrict__ dW,   const float* __restrict__ db,
    const float* __restrict__ decW,
    const float* __restrict__ Kg0, const float* __restrict__ bg0,
    const float* __restrict__ Kc0, const float* __restrict__ bc0,
    const float* __restrict__ Kg1, const float* __restrict__ bg1,
    const float* __restrict__ Kc1, const float* __restrict__ bc1,
    const float* __restrict__ Kg2, const float* __restrict__ bg2,
    const float* __restrict__ Kc2, const float* __restrict__ bc2,
    float* __restrict__ out)
{
    __shared__ __align__(16) uint64_t s_x2[KBLK * XPAD];

    // init x / done (blocks 112..127 idle during the 112-block dense gemm)
    if (blockIdx.x == 112) {
        for (int i = threadIdx.x; i < BB * EMBD; i += TPB)
            g_x[i] = emb[START_TOK * EMBD + (i & (EMBD - 1))];
        if (threadIdx.x < BB) g_done[threadIdx.x] = 0;
    }

    // initial hidden states: y = iv @ dense_W + dense_b
    gemm_phase<LATENT, 0, NSUM, 14, 8, 0>(dW, iv, nullptr, nullptr, s_x2);
    reduce_dense(db);

    for (int s = 0; s < STEPS; s++) {
        gemm_phase<EMBD, L0N, 2 * L0N, 4, 32, 0>(Kg0, g_x,  g_h0, nullptr, s_x2);
        reduce_gates<L0N, 32>(bg0, g_v0);
        gemm_phase<EMBD, L0N, L0N,     2, 64, 1>(Kc0, g_x,  g_h0, g_v0,   s_x2);
        reduce_cand<L0N, 64>(bc0, g_v0, g_h0, g_n0);

        gemm_phase<L0N,  L1N, 2 * L1N, 8, 16, 0>(Kg1, g_n0, g_h1, nullptr, s_x2);
        reduce_gates<L1N, 16>(bg1, g_v1);
        gemm_phase<L0N,  L1N, L1N,     4, 32, 1>(Kc1, g_n0, g_h1, g_v1,   s_x2);
        reduce_cand<L1N, 32>(bc1, g_v1, g_h1, g_n1);

        gemm_phase<L1N,  L2N, 2 * L2N, 16, 8, 0>(Kg2, g_n1, g_h2, nullptr, s_x2);
        reduce_gates<L2N, 8>(bg2, g_v2);
        gemm_phase<L1N,  L2N, L2N,     8, 16, 1>(Kc2, g_n1, g_h2, g_v2,   s_x2);
        reduce_cand<L2N, 16>(bc2, g_v2, g_h2, g_n2);

        decode_phase(decW, emb, out, s);
    }
}

// ---------------- launch ----------------
extern "C" void kernel_launch(void* const* d_in, const int* in_sizes, int n_in,
                              void* d_out, int out_size)
{
    const float* iv   = (const float*)d_in[0];
    const float* emb  = (const float*)d_in[1];
    const float* dW   = (const float*)d_in[2];
    const float* db   = (const float*)d_in[3];
    const float* decW = (const float*)d_in[4];
    const float* Kg0  = (const float*)d_in[5];
    const float* bg0  = (const float*)d_in[6];
    const float* Kc0  = (const float*)d_in[7];
    const float* bc0  = (const float*)d_in[8];
    const float* Kg1  = (const float*)d_in[9];
    const float* bg1  = (const float*)d_in[10];
    const float* Kc1  = (const float*)d_in[11];
    const float* bc1  = (const float*)d_in[12];
    const float* Kg2  = (const float*)d_in[13];
    const float* bg2  = (const float*)d_in[14];
    const float* Kc2  = (const float*)d_in[15];
    const float* bc2  = (const float*)d_in[16];
    float* out = (float*)d_out;

    decoder_kernel<<<GRID, TPB>>>(iv, emb, dW, db, decW,
                                  Kg0, bg0, Kc0, bc0,
                                  Kg1, bg1, Kc1, bc1,
                                  Kg2, bg2, Kc2, bc2, out);
}

// round 17
// speedup vs baseline: 2.2324x; 1.0139x over previous
#include <cuda_runtime.h>
#include <cstdint>

// ---------------- problem constants ----------------
#define BB 64
#define VOC 40
#define EMBD 32
#define L0N 512
#define L1N 1024
#define L2N 2048
#define NSUM (L0N + L1N + L2N)   // 3584
#define LATENT 512
#define STEPS 50
#define START_TOK 39
#define LOGITS_OFF (BB * STEPS)  // 3200

#define GRID 128
#define TPB  512
#define KBLK 16          // k's per smem weight tile
#define TILE_B (KBLK * 1024)   // bytes per weight tile (16 k x 256 cols x 4B)
#define XPAD 66          // smem x row stride (uint64 units), even -> 16B aligned rows

// ---------------- persistent device state (no allocation allowed) ----------------
__device__ float g_h0[BB * L0N];
__device__ float g_h1[BB * L1N];
__device__ float g_h2[BB * L2N];
__device__ float g_n0[BB * L0N];
__device__ float g_n1[BB * L1N];
__device__ float g_n2[BB * L2N];
__device__ float g_v0[BB * 2 * L0N];
__device__ float g_v1[BB * 2 * L1N];
__device__ float g_v2[BB * 2 * L2N];
__device__ float g_x[BB * EMBD];
__device__ int   g_done[BB];
__device__ float g_scr[2 << 20];            // 8MB split-K partial sums

// grid barrier state (monotonic generation; safe across graph replays) — proven
__device__ unsigned          g_barcnt = 0;
__device__ volatile unsigned g_bargen = 0;

// ---------------- helpers ----------------
__device__ __forceinline__ void ffma2(uint64_t& d, uint64_t a, uint64_t b) {
    asm("fma.rn.f32x2 %0, %1, %2, %0;" : "+l"(d) : "l"(a), "l"(b));
}
__device__ __forceinline__ uint64_t pack2(float lo, float hi) {
    uint64_t r;
    asm("mov.b64 %0, {%1, %2};" : "=l"(r) : "f"(lo), "f"(hi));
    return r;
}
__device__ __forceinline__ void unpack2(uint64_t v, float& lo, float& hi) {
    asm("mov.b64 {%0, %1}, %2;" : "=f"(lo), "=f"(hi) : "l"(v));
}
__device__ __forceinline__ float sigmoidf_(float x) {
    return 1.0f / (1.0f + expf(-x));
}
__device__ __forceinline__ void cp_async16(uint32_t saddr, const void* g) {
    asm volatile("cp.async.cg.shared.global [%0], [%1], 16;"
                 :: "r"(saddr), "l"(g) : "memory");
}
#define CP_COMMIT() asm volatile("cp.async.commit_group;" ::: "memory")
#define CP_WAIT1()  asm volatile("cp.async.wait_group 1;" ::: "memory")
#define CP_WAIT0()  asm volatile("cp.async.wait_group 0;" ::: "memory")

// all 128 blocks are co-resident (GRID < 148 SMs) -> spin barrier is safe
__device__ __forceinline__ void grid_bar() {
    __syncthreads();
    if (threadIdx.x == 0) {
        unsigned gen = g_bargen;
        __threadfence();
        if (atomicAdd(&g_barcnt, 1u) == GRID - 1) {
            g_barcnt = 0;
            __threadfence();
            g_bargen = gen + 1;
        } else {
            while (g_bargen == gen) { }
            __threadfence();
        }
    }
    __syncthreads();
}

// ---------------- split-K GEMM phase (R4 dataflow; cp.async double-buffered weights) ----------------
// Block tile: 256 cols x 64 rows, K-chunked. Thread: 8 cols (4 pairs) x 4 rows.
// Weight tiles (16 k x 1KB) streamed gmem->smem via cp.async, double buffered:
// tile t+1 prefetches while tile t computes -> DRAM latency hidden, lines loaded once/block.
// Partials -> g_scr[chunk][row][colpair].
// MODE 0: input = concat[x, h];  MODE 1: input = concat[x, r*h] (r = 1st half of v)
template<int IN, int OUT, int NCOL, int TILES, int CHUNKS, int MODE>
__device__ __forceinline__ void gemm_phase(
    const float* __restrict__ W,
    const float* __restrict__ xbuf,
    const float* __restrict__ hbuf,
    const float* __restrict__ vbuf,
    char* __restrict__ s_w,        // smem: 2 * TILE_B bytes
    uint64_t* __restrict__ s_x2)   // smem: KBLK * XPAD uint64
{
    constexpr int KTOT = IN + OUT;
    constexpr int KC   = (KTOT + CHUNKS - 1) / CHUNKS;

    const int bid = blockIdx.x;
    if (bid < TILES * CHUNKS) {
        const int tile  = bid % TILES;
        const int chunk = bid / TILES;
        const int k0 = chunk * KC;
        const int k1 = (k0 + KC < KTOT) ? (k0 + KC) : KTOT;
        const int jbase = tile * 256;
        const int tid = threadIdx.x;
        const int c  = tid & 31;   // col-thread: 8 cols
        const int rg = tid >> 5;   // row-group: 4 rows

        uint64_t acc[4][4];
#pragma unroll
        for (int cp = 0; cp < 4; cp++)
#pragma unroll
            for (int r = 0; r < 4; r++) acc[cp][r] = 0ull;

        const uint32_t sw_base = (uint32_t)__cvta_generic_to_shared(s_w);
        const float* Wt = W + jbase;   // tile column base

        const int nkb = (k1 - k0 + KBLK - 1) / KBLK;

        // prologue: stream tile 0
        {
            const int kt0 = (k1 - k0 < KBLK) ? (k1 - k0) : KBLK;
            for (int idx = tid; idx < kt0 * 64; idx += TPB) {
                const int row = idx >> 6, ch = idx & 63;
                cp_async16(sw_base + (row << 10) + (ch << 4),
                           Wt + (size_t)(k0 + row) * NCOL + ch * 4);
            }
            CP_COMMIT();
        }

        int buf = 0;
        for (int ti = 0; ti < nkb; ti++) {
            const int kb = k0 + ti * KBLK;
            const int kt = (k1 - kb < KBLK) ? (k1 - kb) : KBLK;

            __syncthreads();   // protects s_x2 and the prefetch target buffer

            // stage x for [kb, kb+kt): duplicated (v,v) pairs
            for (int idx = tid; idx < 64 * KBLK; idx += TPB) {
                const int kk  = idx & (KBLK - 1);
                const int row = idx >> 4;
                if (kk < kt) {
                    const int kg = kb + kk;
                    float val;
                    if (kg < IN) {
                        val = xbuf[row * IN + kg];
                    } else {
                        const int q = kg - IN;
                        const float hv = hbuf[row * OUT + q];
                        if (MODE == 1)
                            val = vbuf[row * (2 * OUT) + q] * hv;
                        else
                            val = hv;
                    }
                    s_x2[kk * XPAD + row] = pack2(val, val);
                }
            }

            // prefetch next tile into the other buffer, then wait for current tile
            if (ti + 1 < nkb) {
                const int kbn = kb + KBLK;
                const int ktn = (k1 - kbn < KBLK) ? (k1 - kbn) : KBLK;
                const uint32_t dst = sw_base + (uint32_t)((buf ^ 1) * TILE_B);
                for (int idx = tid; idx < ktn * 64; idx += TPB) {
                    const int row = idx >> 6, ch = idx & 63;
                    cp_async16(dst + (row << 10) + (ch << 4),
                               Wt + (size_t)(kbn + row) * NCOL + ch * 4);
                }
                CP_COMMIT();
                CP_WAIT1();   // current tile's group complete; next stays in flight
            } else {
                CP_WAIT0();
            }
            __syncthreads();   // x + current weight tile visible block-wide

            // compute from smem
            const char* wb_base = s_w + buf * TILE_B + c * 32;
#pragma unroll 4
            for (int kk = 0; kk < kt; kk++) {
                const char* wr = wb_base + (kk << 10);
                const ulonglong2 wa  = *reinterpret_cast<const ulonglong2*>(wr);
                const ulonglong2 wb2 = *reinterpret_cast<const ulonglong2*>(wr + 16);
                const uint64_t* xr = s_x2 + kk * XPAD + (rg << 2);
                const ulonglong2 x01 = *reinterpret_cast<const ulonglong2*>(xr);
                const ulonglong2 x23 = *reinterpret_cast<const ulonglong2*>(xr + 2);
                const uint64_t xd[4] = {x01.x, x01.y, x23.x, x23.y};
#pragma unroll
                for (int r = 0; r < 4; r++) {
                    ffma2(acc[0][r], wa.x,  xd[r]);
                    ffma2(acc[1][r], wa.y,  xd[r]);
                    ffma2(acc[2][r], wb2.x, xd[r]);
                    ffma2(acc[3][r], wb2.y, xd[r]);
                }
            }
            buf ^= 1;
        }

        // epilogue: partials to scratch (uint64 = col-pair), coalesced
        uint64_t* scr = reinterpret_cast<uint64_t*>(g_scr);
#pragma unroll
        for (int r = 0; r < 4; r++) {
            const int row = (rg << 2) + r;
            uint64_t* dst = scr + (size_t)(chunk * 64 + row) * (NCOL / 2)
                                + (jbase >> 1) + (c << 2);
#pragma unroll
            for (int cp = 0; cp < 4; cp++) dst[cp] = acc[cp][r];
        }
    }
    grid_bar();
}

// ---------------- reduce + activation phases (R4-exact) ----------------
template<int OUT, int CHUNKS>
__device__ __forceinline__ void reduce_gates(const float* __restrict__ bg,
                                             float* __restrict__ v)
{
    const int NP = 64 * OUT;   // col-pairs (NCOL/2 = OUT)
    const uint64_t* scr = reinterpret_cast<const uint64_t*>(g_scr);
    for (int p = blockIdx.x * TPB + threadIdx.x; p < NP; p += GRID * TPB) {
        const int row = p / OUT;
        const int jp  = p - row * OUT;
        float s0 = 0.f, s1 = 0.f;
#pragma unroll 8
        for (int ch = 0; ch < CHUNKS; ch++) {
            float a, b;
            unpack2(scr[(size_t)(ch * 64 + row) * OUT + jp], a, b);
            s0 += a; s1 += b;
        }
        const int j = jp * 2;
        v[row * (2 * OUT) + j]     = sigmoidf_(s0 + bg[j]);
        v[row * (2 * OUT) + j + 1] = sigmoidf_(s1 + bg[j + 1]);
    }
    grid_bar();
}

template<int OUT, int CHUNKS>
__device__ __forceinline__ void reduce_cand(const float* __restrict__ bc,
                                            const float* __restrict__ v,
                                            const float* __restrict__ h,
                                            float* __restrict__ n)
{
    constexpr int HP = OUT / 2;
    const int NP = 64 * HP;
    const uint64_t* scr = reinterpret_cast<const uint64_t*>(g_scr);
    for (int p = blockIdx.x * TPB + threadIdx.x; p < NP; p += GRID * TPB) {
        const int row = p / HP;
        const int jp  = p - row * HP;
        float s0 = 0.f, s1 = 0.f;
#pragma unroll 8
        for (int ch = 0; ch < CHUNKS; ch++) {
            float a, b;
            unpack2(scr[(size_t)(ch * 64 + row) * HP + jp], a, b);
            s0 += a; s1 += b;
        }
        const int j = jp * 2;
#pragma unroll
        for (int t = 0; t < 2; t++) {
            const float cv = tanhf(((t == 0) ? s0 : s1) + bc[j + t]);
            const float z  = v[row * (2 * OUT) + OUT + j + t];
            const float hv = h[row * OUT + j + t];
            n[row * OUT + j + t] = z * hv + (1.0f - z) * cv;
        }
    }
    grid_bar();
}

__device__ __forceinline__ void reduce_dense(const float* __restrict__ db)
{
    constexpr int HP = NSUM / 2;   // 1792
    const int NP = 64 * HP;
    const uint64_t* scr = reinterpret_cast<const uint64_t*>(g_scr);
    for (int p = blockIdx.x * TPB + threadIdx.x; p < NP; p += GRID * TPB) {
        const int row = p / HP;
        const int jp  = p - row * HP;
        float s0 = 0.f, s1 = 0.f;
#pragma unroll
        for (int ch = 0; ch < 8; ch++) {
            float a, b;
            unpack2(scr[(size_t)(ch * 64 + row) * HP + jp], a, b);
            s0 += a; s1 += b;
        }
        const int j = jp * 2;
        const float y0 = s0 + db[j];
        const float y1 = s1 + db[j + 1];
        if (j < L0N) {
            g_h0[row * L0N + j] = y0; g_h0[row * L0N + j + 1] = y1;
        } else if (j < L0N + L1N) {
            g_h1[row * L1N + (j - L0N)] = y0; g_h1[row * L1N + (j - L0N) + 1] = y1;
        } else {
            g_h2[row * L2N + (j - L0N - L1N)] = y0; g_h2[row * L2N + (j - L0N - L1N) + 1] = y1;
        }
    }
    grid_bar();
}

// ---------------- decode phase (R4-exact) ----------------
__device__ __forceinline__ void decode_phase(const float* __restrict__ decW,
                                             const float* __restrict__ emb,
                                             float* __restrict__ out, int step)
{
    if (blockIdx.x < BB) {
        __shared__ float s_logit[VOC];
        __shared__ int s_idx, s_d0;
        const int b    = blockIdx.x;
        const int tid  = threadIdx.x;
        const int w    = tid >> 5;      // 16 warps
        const int lane = tid & 31;

        if (w < 8) {   // 8 warps x 5 logit cols
            float acc[5];
#pragma unroll
            for (int jj = 0; jj < 5; jj++) acc[jj] = 0.0f;

            const float* n2row = g_n2 + b * L2N;
            for (int k = lane; k < L2N; k += 32) {
                const float xv = n2row[k];
                const float* wr = decW + k * VOC + w * 5;
#pragma unroll
                for (int jj = 0; jj < 5; jj++) acc[jj] += xv * wr[jj];
            }
#pragma unroll
            for (int jj = 0; jj < 5; jj++) {
                float s = acc[jj];
#pragma unroll
                for (int off = 16; off > 0; off >>= 1)
                    s += __shfl_down_sync(0xffffffffu, s, off);
                if (lane == 0) s_logit[w * 5 + jj] = s;
            }
        }
        __syncthreads();

        if (tid == 0) {
            const int d0 = g_done[b];
            float best = s_logit[0];
            int bi = 0;
            for (int jj = 1; jj < VOC; jj++) {
                const float lv = s_logit[jj];
                if (lv > best) { best = lv; bi = jj; }   // first-max on ties
            }
            s_idx = bi;
            s_d0  = d0;
            out[b * STEPS + step] = (float)(d0 ? 0 : bi);   // STOP_TOK == 0
            g_done[b] = d0 | (bi == 0);
        }
        __syncthreads();

        const int d0  = s_d0;
        const int idx = s_idx;

        float* lo = out + LOGITS_OFF + (b * STEPS + step) * VOC;
        for (int jj = tid; jj < VOC; jj += TPB)
            lo[jj] = d0 ? 0.0f : s_logit[jj];

        if (!d0) {
            for (int q = tid; q < L0N; q += TPB) g_h0[b * L0N + q] = g_n0[b * L0N + q];
            for (int q = tid; q < L1N; q += TPB) g_h1[b * L1N + q] = g_n1[b * L1N + q];
            for (int q = tid; q < L2N; q += TPB) g_h2[b * L2N + q] = g_n2[b * L2N + q];
            if (tid < EMBD) g_x[b * EMBD + tid] = emb[idx * EMBD + tid];
        }
    }
    grid_bar();
}

// ---------------- the single persistent kernel ----------------
__global__ void __launch_bounds__(TPB, 1) decoder_kernel(
    const float* __restrict__ iv,   const float* __restrict__ emb,
    const float* __restrict__ dW,   const float* __restrict__ db,
    const float* __restrict__ decW,
    const float* __restrict__ Kg0, const float* __restrict__ bg0,
    const float* __restrict__ Kc0, const float* __restrict__ bc0,
    const float* __restrict__ Kg1, const float* __restrict__ bg1,
    const float* __restrict__ Kc1, const float* __restrict__ bc1,
    const float* __restrict__ Kg2, const float* __restrict__ bg2,
    const float* __restrict__ Kc2, const float* __restrict__ bc2,
    float* __restrict__ out)
{
    __shared__ __align__(16) char     s_w[2 * TILE_B];       // 32 KB weight tiles
    __shared__ __align__(16) uint64_t s_x2[KBLK * XPAD];     // 8.25 KB x staging

    // init x / done (blocks 112..127 idle during the 112-block dense gemm)
    if (blockIdx.x == 112) {
        for (int i = threadIdx.x; i < BB * EMBD; i += TPB)
            g_x[i] = emb[START_TOK * EMBD + (i & (EMBD - 1))];
        if (threadIdx.x < BB) g_done[threadIdx.x] = 0;
    }

    // initial hidden states: y = iv @ dense_W + dense_b
    gemm_phase<LATENT, 0, NSUM, 14, 8, 0>(dW, iv, nullptr, nullptr, s_w, s_x2);
    reduce_dense(db);

    for (int s = 0; s < STEPS; s++) {
        gemm_phase<EMBD, L0N, 2 * L0N, 4, 32, 0>(Kg0, g_x,  g_h0, nullptr, s_w, s_x2);
        reduce_gates<L0N, 32>(bg0, g_v0);
        gemm_phase<EMBD, L0N, L0N,     2, 64, 1>(Kc0, g_x,  g_h0, g_v0,   s_w, s_x2);
        reduce_cand<L0N, 64>(bc0, g_v0, g_h0, g_n0);

        gemm_phase<L0N,  L1N, 2 * L1N, 8, 16, 0>(Kg1, g_n0, g_h1, nullptr, s_w, s_x2);
        reduce_gates<L1N, 16>(bg1, g_v1);
        gemm_phase<L0N,  L1N, L1N,     4, 32, 1>(Kc1, g_n0, g_h1, g_v1,   s_w, s_x2);
        reduce_cand<L1N, 32>(bc1, g_v1, g_h1, g_n1);

        gemm_phase<L1N,  L2N, 2 * L2N, 16, 8, 0>(Kg2, g_n1, g_h2, nullptr, s_w, s_x2);
        reduce_gates<L2N, 8>(bg2, g_v2);
        gemm_phase<L1N,  L2N, L2N,     8, 16, 1>(Kc2, g_n1, g_h2, g_v2,   s_w, s_x2);
        reduce_cand<L2N, 16>(bc2, g_v2, g_h2, g_n2);

        decode_phase(decW, emb, out, s);
    }
}

// ---------------- launch ----------------
extern "C" void kernel_launch(void* const* d_in, const int* in_sizes, int n_in,
                              void* d_out, int out_size)
{
    const float* iv   = (const float*)d_in[0];
    const float* emb  = (const float*)d_in[1];
    const float* dW   = (const float*)d_in[2];
    const float* db   = (const float*)d_in[3];
    const float* decW = (const float*)d_in[4];
    const float* Kg0  = (const float*)d_in[5];
    const float* bg0  = (const float*)d_in[6];
    const float* Kc0  = (const float*)d_in[7];
    const float* bc0  = (const float*)d_in[8];
    const float* Kg1  = (const float*)d_in[9];
    const float* bg1  = (const float*)d_in[10];
    const float* Kc1  = (const float*)d_in[11];
    const float* bc1  = (const float*)d_in[12];
    const float* Kg2  = (const float*)d_in[13];
    const float* bg2  = (const float*)d_in[14];
    const float* Kc2  = (const float*)d_in[15];
    const float* bc2  = (const float*)d_in[16];
    float* out = (float*)d_out;

    decoder_kernel<<<GRID, TPB>>>(iv, emb, dW, db, decW,
                                  Kg0, bg0, Kc0, bc0,
                                  Kg1, bg1, Kc1, bc1,
                                  Kg2, bg2, Kc2, bc2, out);
}